// round 4
// baseline (speedup 1.0000x reference)
#include <cuda_runtime.h>

// Problem constants (fixed by the reference)
#define BB   4
#define CC   32
#define HH   64
#define WW   64
#define KK   64
#define HWV  (HH*WW)      // 4096
#define BCV  (BB*CC)      // 128
#define CAP  1024         // max support pixels per RF (analysis: <= ~930)
#define NGR  8            // independent k-groups per block
#define GT   128          // threads per group
#define OUTP 1024         // 32*32 outputs per bc

// ---------------- static device scratch (no allocation allowed) -------------
__device__ int  g_cnt[KK];        // support size per k
__device__ int2 g_pk[KK*CAP];     // packed {pixel, bits(rf * log2(e))}

__device__ __forceinline__ float ex2_fast(float y) {
    float r;
    asm("ex2.approx.f32 %0, %1;" : "=f"(r) : "f"(y));
    return r;
}

// ---------------- P1: per-k compact support lists (2 barriers total) --------
// One block of 1024 threads per k. Thread t owns pixels [4t, 4t+4) (float4).
// Warp shfl-scan of per-lane counts + warp0 scan of 32 warp totals gives the
// full-block exclusive prefix in raster order -> deterministic list order.
__global__ __launch_bounds__(1024) void build_k_lists(const float* __restrict__ rfs) {
    const int k    = blockIdx.x;
    const int tid  = threadIdx.x;
    const int lane = tid & 31;
    const int wid  = tid >> 5;

    __shared__ int wtot[32];
    __shared__ int woff[32];

    const float LOG2E = 1.4426950408889634f;
    const float4 r = ((const float4*)(rfs + k*HWV))[tid];
    const int f0 = (r.x != 0.0f), f1 = (r.y != 0.0f), f2 = (r.z != 0.0f), f3 = (r.w != 0.0f);
    const int cnt = f0 + f1 + f2 + f3;

    int s = cnt;                           // warp inclusive scan
    #pragma unroll
    for (int o = 1; o < 32; o <<= 1) {
        int t = __shfl_up_sync(0xffffffffu, s, o);
        if (lane >= o) s += t;
    }
    const int excl = s - cnt;
    if (lane == 31) wtot[wid] = s;
    __syncthreads();
    if (wid == 0) {
        int v = wtot[lane], ss = v;        // scan 32 warp totals
        #pragma unroll
        for (int o = 1; o < 32; o <<= 1) {
            int t = __shfl_up_sync(0xffffffffu, ss, o);
            if (lane >= o) ss += t;
        }
        woff[lane] = ss - v;
        if (lane == 31) g_cnt[k] = (ss < CAP) ? ss : CAP;
    }
    __syncthreads();

    int base = woff[wid] + excl;
    const int p0 = tid * 4;
    int2* __restrict__ dst = g_pk + k*CAP;
    if (f0 && base < CAP) { dst[base] = make_int2(p0,     __float_as_int(r.x * LOG2E)); base++; }
    if (f1 && base < CAP) { dst[base] = make_int2(p0 + 1, __float_as_int(r.y * LOG2E)); base++; }
    if (f2 && base < CAP) { dst[base] = make_int2(p0 + 2, __float_as_int(r.z * LOG2E)); base++; }
    if (f3 && base < CAP) { dst[base] = make_int2(p0 + 3, __float_as_int(r.w * LOG2E)); base++; }
}

// ---------------- K1: everything fused, one block per bc --------------------
// exp(v - m)/(exp(-m) + sum exp(v - m)) == exp(v)/(1 + sum exp(v)).
// 8 groups of 128 threads run independently (no block barriers in main loop);
// group g handles k = g, g+8, ... into a private smem h accumulator.
// Per k: ONE named barrier (bar.sync g+1, 128). Ordering proof: a thread
// reaches bar(kk+1) only after its RMW(kk), and RMW(kk+1) starts only after
// bar(kk+1) releases -> cross-warp RMWs of different k never race; within one
// k all pixels are distinct. gsum is parity double-buffered so iter kk+1's
// partial writes can't clobber a slow thread's iter-kk reads.
__global__ __launch_bounds__(1024) void rf_all(const float* __restrict__ u,
                                               float* __restrict__ out) {
    extern __shared__ float smem[];
    float* us    = smem;                 // [HWV]
    float* hsall = us + HWV;             // [NGR][HWV]
    float* gsum  = hsall + NGR*HWV;      // [NGR][2][4]
    int*   scnt  = (int*)(gsum + NGR*8); // [KK]

    const int bc   = blockIdx.x;
    const int tid  = threadIdx.x;
    const int g    = tid >> 7;           // group 0..7 (warp-aligned)
    const int gt   = tid & (GT - 1);     // thread within group
    const int lane = tid & 31;
    const int gw   = (tid >> 5) & 3;     // warp within group

    const float* __restrict__ up = u + bc*HWV;
    #pragma unroll
    for (int i = tid; i < HWV; i += 1024) us[i] = up[i];
    float* __restrict__ hg = hsall + g*HWV;
    #pragma unroll
    for (int i = gt; i < HWV; i += GT) hg[i] = 0.0f;
    if (tid < KK) scnt[tid] = g_cnt[tid];
    __syncthreads();

    float* const gs = gsum + g*8;        // this group's two 4-entry buffers

    for (int kk = 0; kk < KK/NGR; kk++) {
        const int k = g + kk*NGR;
        const int n = scnt[k];
        const int4* __restrict__ pr = (const int4*)(g_pk + k*CAP) + 4*gt;
        const int ib = 8*gt;

        float ev[8];
        int   pv[8];
        float lsum = 0.0f;
        #pragma unroll
        for (int j = 0; j < 4; j++) {
            const int4 v = pr[j];        // always in-bounds (CAP array)
            if (ib + 2*j < n) {
                pv[2*j] = v.x;
                const float e = ex2_fast(us[v.x] * __int_as_float(v.y));
                ev[2*j] = e; lsum += e;
            } else ev[2*j] = 0.0f;
            if (ib + 2*j + 1 < n) {
                pv[2*j+1] = v.z;
                const float e = ex2_fast(us[v.z] * __int_as_float(v.w));
                ev[2*j+1] = e; lsum += e;
            } else ev[2*j+1] = 0.0f;
        }

        #pragma unroll
        for (int o = 16; o > 0; o >>= 1) lsum += __shfl_down_sync(0xffffffffu, lsum, o);
        float* const gb = gs + (kk & 1)*4;
        if (lane == 0) gb[gw] = lsum;
        asm volatile("bar.sync %0, %1;" :: "r"(g + 1), "n"(GT) : "memory");

        const float inv = 1.0f / (1.0f + (gb[0] + gb[1] + gb[2] + gb[3]));
        #pragma unroll
        for (int j = 0; j < 8; j++)
            if (ev[j] != 0.0f) hg[pv[j]] += ev[j] * inv;   // e >= 2^-8 > 0 always
    }
    __syncthreads();

    // merge 8 partials + 2x2 block max pool; one output per thread
    const int oh = tid >> 5;
    const int ow = tid & 31;
    float best = 0.0f;                   // h >= 0 always (matches reference)
    #pragma unroll
    for (int dy = 0; dy < 2; dy++) {
        #pragma unroll
        for (int dx = 0; dx < 2; dx++) {
            const int p = (2*oh + dy)*WW + (2*ow + dx);
            float s = 0.0f;
            #pragma unroll
            for (int q = 0; q < NGR; q++) s += hsall[q*HWV + p];
            best = fmaxf(best, s);
        }
    }
    out[bc*OUTP + tid] = best;
}

// ---------------- launch -----------------------------------------------------
#define RF_ALL_SMEM ((HWV + NGR*HWV + NGR*8)*4 + KK*4)   // 147,968 B

extern "C" void kernel_launch(void* const* d_in, const int* in_sizes, int n_in,
                              void* d_out, int out_size) {
    const float* u   = (const float*)d_in[0];   // (4,32,64,64)
    const float* rfs = (const float*)d_in[1];   // (64,64,64)
    float* out = (float*)d_out;                 // (4,32,32,32)

    cudaFuncSetAttribute(rf_all, cudaFuncAttributeMaxDynamicSharedMemorySize, RF_ALL_SMEM);

    build_k_lists<<<KK, 1024>>>(rfs);
    rf_all       <<<BCV, 1024, RF_ALL_SMEM>>>(u, out);
}

// round 5
// speedup vs baseline: 1.6383x; 1.6383x over previous
#include <cuda_runtime.h>

// Problem constants (fixed by the reference)
#define BB   4
#define CC   32
#define HH   64
#define WW   64
#define KK   64
#define HWV  (HH*WW)      // 4096
#define BCV  (BB*CC)      // 128
#define CAP  1024         // max support pixels per RF (analysis: <= ~930)
#define NGR  8            // independent k-groups per block
#define GT   128          // threads per group
#define OUTP 1024         // 32*32 outputs per bc

// ---------------- static device scratch (no allocation allowed) -------------
__device__ int  g_cnt[KK];        // support size per k
__device__ int2 g_pk[KK*CAP];     // packed {pixel, bits(rf * log2(e))}

__device__ __forceinline__ float ex2_fast(float y) {
    float r;
    asm("ex2.approx.f32 %0, %1;" : "=f"(r) : "f"(y));
    return r;
}

// ---------------- P1: per-k compact support lists (2 barriers total) --------
// One block of 1024 threads per k. Thread t owns pixels [4t, 4t+4) (float4).
// Warp shfl-scan of per-lane counts + warp0 scan of 32 warp totals gives the
// full-block exclusive prefix in raster order -> deterministic list order.
__global__ __launch_bounds__(1024) void build_k_lists(const float* __restrict__ rfs) {
    const int k    = blockIdx.x;
    const int tid  = threadIdx.x;
    const int lane = tid & 31;
    const int wid  = tid >> 5;

    __shared__ int wtot[32];
    __shared__ int woff[32];

    const float LOG2E = 1.4426950408889634f;
    const float4 r = ((const float4*)(rfs + k*HWV))[tid];
    const int f0 = (r.x != 0.0f), f1 = (r.y != 0.0f), f2 = (r.z != 0.0f), f3 = (r.w != 0.0f);
    const int cnt = f0 + f1 + f2 + f3;

    int s = cnt;                           // warp inclusive scan
    #pragma unroll
    for (int o = 1; o < 32; o <<= 1) {
        int t = __shfl_up_sync(0xffffffffu, s, o);
        if (lane >= o) s += t;
    }
    const int excl = s - cnt;
    if (lane == 31) wtot[wid] = s;
    __syncthreads();
    if (wid == 0) {
        int v = wtot[lane], ss = v;        // scan 32 warp totals
        #pragma unroll
        for (int o = 1; o < 32; o <<= 1) {
            int t = __shfl_up_sync(0xffffffffu, ss, o);
            if (lane >= o) ss += t;
        }
        woff[lane] = ss - v;
        if (lane == 31) g_cnt[k] = (ss < CAP) ? ss : CAP;
    }
    __syncthreads();

    int base = woff[wid] + excl;
    const int p0 = tid * 4;
    int2* __restrict__ dst = g_pk + k*CAP;
    if (f0 && base < CAP) { dst[base] = make_int2(p0,     __float_as_int(r.x * LOG2E)); base++; }
    if (f1 && base < CAP) { dst[base] = make_int2(p0 + 1, __float_as_int(r.y * LOG2E)); base++; }
    if (f2 && base < CAP) { dst[base] = make_int2(p0 + 2, __float_as_int(r.z * LOG2E)); base++; }
    if (f3 && base < CAP) { dst[base] = make_int2(p0 + 3, __float_as_int(r.w * LOG2E)); base++; }
}

// ---------------- K1: everything fused, one block per bc --------------------
// exp(v - m)/(exp(-m) + sum exp(v - m)) == exp(v)/(1 + sum exp(v)).
// 8 groups of 128 threads run independently; group g handles k = g, g+8, ...
// into a private smem h accumulator. Element assignment is STRIDED
// (thread gt owns list elements gt, gt+GT, ...): consecutive lanes touch
// consecutive list elements -> consecutive pixels -> conflict-free smem
// gathers/RMWs and fully coalesced LDG.64 on the list.
// Per k: ONE named barrier (bar.sync g+1, 128). Ordering proof: a thread
// reaches bar(kk+1) only after its RMW(kk), and RMW(kk+1) starts only after
// bar(kk+1) releases -> cross-warp RMWs of different k never race; within one
// k all pixels are distinct. gsum is parity double-buffered so iter kk+1's
// partial writes can't clobber a slow thread's iter-kk reads.
__global__ __launch_bounds__(1024) void rf_all(const float* __restrict__ u,
                                               float* __restrict__ out) {
    extern __shared__ float smem[];
    float* us    = smem;                 // [HWV]
    float* hsall = us + HWV;             // [NGR][HWV]
    float* gsum  = hsall + NGR*HWV;      // [NGR][2][4]
    int*   scnt  = (int*)(gsum + NGR*8); // [KK]

    const int bc   = blockIdx.x;
    const int tid  = threadIdx.x;
    const int g    = tid >> 7;           // group 0..7 (warp-aligned)
    const int gt   = tid & (GT - 1);     // thread within group
    const int lane = tid & 31;
    const int gw   = (tid >> 5) & 3;     // warp within group

    const float* __restrict__ up = u + bc*HWV;
    #pragma unroll
    for (int i = tid; i < HWV; i += 1024) us[i] = up[i];
    float* __restrict__ hg = hsall + g*HWV;
    #pragma unroll
    for (int i = gt; i < HWV; i += GT) hg[i] = 0.0f;
    if (tid < KK) scnt[tid] = g_cnt[tid];
    __syncthreads();

    float* const gs = gsum + g*8;        // this group's two 4-entry buffers

    for (int kk = 0; kk < KK/NGR; kk++) {
        const int k = g + kk*NGR;
        const int n = scnt[k];
        const int2* __restrict__ pr = g_pk + k*CAP + gt;

        // strided elements: gt + j*GT, j = 0..7 (CAP = 8*GT)
        int2 vv[8];
        #pragma unroll
        for (int j = 0; j < 8; j++) vv[j] = pr[j*GT];  // always in-bounds

        float ev[8];
        float lsum = 0.0f;
        #pragma unroll
        for (int j = 0; j < 8; j++) {
            if (gt + j*GT < n) {
                const float e = ex2_fast(us[vv[j].x] * __int_as_float(vv[j].y));
                ev[j] = e; lsum += e;
            } else ev[j] = 0.0f;
        }

        #pragma unroll
        for (int o = 16; o > 0; o >>= 1) lsum += __shfl_down_sync(0xffffffffu, lsum, o);
        float* const gb = gs + (kk & 1)*4;
        if (lane == 0) gb[gw] = lsum;
        asm volatile("bar.sync %0, %1;" :: "r"(g + 1), "n"(GT) : "memory");

        const float inv = 1.0f / (1.0f + (gb[0] + gb[1] + gb[2] + gb[3]));
        #pragma unroll
        for (int j = 0; j < 8; j++)
            if (ev[j] != 0.0f) hg[vv[j].x] += ev[j] * inv;  // e >= 2^-8 > 0 always
    }
    __syncthreads();

    // merge 8 partials + 2x2 block max pool; one output per thread
    const int oh = tid >> 5;
    const int ow = tid & 31;
    float best = 0.0f;                   // h >= 0 always (matches reference)
    #pragma unroll
    for (int dy = 0; dy < 2; dy++) {
        #pragma unroll
        for (int dx = 0; dx < 2; dx++) {
            const int p = (2*oh + dy)*WW + (2*ow + dx);
            float s = 0.0f;
            #pragma unroll
            for (int q = 0; q < NGR; q++) s += hsall[q*HWV + p];
            best = fmaxf(best, s);
        }
    }
    out[bc*OUTP + tid] = best;
}

// ---------------- launch -----------------------------------------------------
#define RF_ALL_SMEM ((HWV + NGR*HWV + NGR*8)*4 + KK*4)   // 147,968 B

extern "C" void kernel_launch(void* const* d_in, const int* in_sizes, int n_in,
                              void* d_out, int out_size) {
    const float* u   = (const float*)d_in[0];   // (4,32,64,64)
    const float* rfs = (const float*)d_in[1];   // (64,64,64)
    float* out = (float*)d_out;                 // (4,32,32,32)

    cudaFuncSetAttribute(rf_all, cudaFuncAttributeMaxDynamicSharedMemorySize, RF_ALL_SMEM);

    build_k_lists<<<KK, 1024>>>(rfs);
    rf_all       <<<BCV, 1024, RF_ALL_SMEM>>>(u, out);
}